// round 2
// baseline (speedup 1.0000x reference)
#include <cuda_runtime.h>
#include <cuda_bf16.h>
#include <math.h>

// Problem constants (fixed shapes for this problem)
#define NN 100000
#define EE 1600000
#define DD 64
#define CC 2

// Static device scratch (no allocation allowed)
__device__ int    g_row[EE];
__device__ int    g_col[EE];
__device__ int    g_deg[NN];
__device__ float  g_dinv[NN];
__device__ float2 g_y0[NN];
__device__ float2 g_y1[NN];
__device__ float2 g_y2[NN];
__device__ int    g_is64;   // 1 if edge buffer is int64, 0 if int32

// ---------------- kernels ----------------

// Detect edge_index element width. If the data is int64, every value is a
// valid node id < NN. If it is int32, interpreting pairs as int64 yields
// lo | (hi<<32) with hi = the next (generally nonzero) index -> huge values.
__global__ void k_detect(const void* __restrict__ edge, int n) {
    const long long* e64 = (const long long*)edge;
    int ok = 1;
    #pragma unroll 1
    for (int i = 0; i < 64; i++) {
        long long v = e64[i];
        if (v < 0 || v >= (long long)n) { ok = 0; break; }
    }
    g_is64 = ok;
}

// deg[i] = 1 (self loop)
__global__ void k_init_deg(int n) {
    int i = blockIdx.x * blockDim.x + threadIdx.x;
    if (i < n) g_deg[i] = 1;
}

// convert edge_index -> int32 row/col, count in-degree of col
__global__ void k_count(const void* __restrict__ edge, int e, int n) {
    int i = blockIdx.x * blockDim.x + threadIdx.x;
    if (i >= e) return;
    int r, c;
    if (g_is64) {
        const long long* e64 = (const long long*)edge;
        r = (int)e64[i];
        c = (int)e64[e + i];
    } else {
        const int* e32 = (const int*)edge;
        r = e32[i];
        c = e32[e + i];
    }
    // Bounds guard: never trap on unexpected layouts.
    if ((unsigned)r >= (unsigned)n || (unsigned)c >= (unsigned)n) {
        g_row[i] = 0; g_col[i] = 0;  // will be overwritten/never used on good data
        return;
    }
    g_row[i] = r;
    g_col[i] = c;
    atomicAdd(&g_deg[c], 1);
}

// dinv = rsqrt(deg)
__global__ void k_dinv(int n) {
    int i = blockIdx.x * blockDim.x + threadIdx.x;
    if (i < n) g_dinv[i] = rsqrtf((float)g_deg[i]);
}

// y0[i] = x[i] @ W.T  (D=64 -> C=2), one warp per node
__global__ void k_proj(const float* __restrict__ x, const float* __restrict__ W, int n) {
    __shared__ float sW[2 * DD];
    int t = threadIdx.x;
    if (t < 2 * DD) sW[t] = W[t];
    __syncthreads();
    int gw = (blockIdx.x * blockDim.x + t) >> 5;
    int lane = t & 31;
    if (gw >= n) return;
    const float* xr = x + (size_t)gw * DD;
    float a  = xr[lane];
    float b2 = xr[lane + 32];
    float s0 = a * sW[lane]      + b2 * sW[lane + 32];
    float s1 = a * sW[DD + lane] + b2 * sW[DD + lane + 32];
    #pragma unroll
    for (int o = 16; o; o >>= 1) {
        s0 += __shfl_xor_sync(0xffffffffu, s0, o);
        s1 += __shfl_xor_sync(0xffffffffu, s1, o);
    }
    if (lane == 0) g_y0[gw] = make_float2(s0, s1);
}

// dst[i] = dinv[i]^2 * src[i]   (self-loop term; also initializes dst)
template <int WHICH>  // 1: y0->y1, 2: y1->y2
__global__ void k_self(int n) {
    int i = blockIdx.x * blockDim.x + threadIdx.x;
    if (i >= n) return;
    float d = g_dinv[i];
    float s = d * d;
    float2 v = (WHICH == 1) ? g_y0[i] : g_y1[i];
    float2 o = make_float2(s * v.x, s * v.y);
    if (WHICH == 1) g_y1[i] = o; else g_y2[i] = o;
}

// dst[col] += dinv[row]*dinv[col] * src[row]   (edge scatter)
template <int WHICH>  // 1: y0->y1, 2: y1->y2
__global__ void k_edge(int e, int n) {
    int i = blockIdx.x * blockDim.x + threadIdx.x;
    if (i >= e) return;
    int r = g_row[i];
    int c = g_col[i];
    if ((unsigned)r >= (unsigned)n || (unsigned)c >= (unsigned)n) return;
    float nrm = g_dinv[r] * g_dinv[c];
    float2 v = (WHICH == 1) ? g_y0[r] : g_y1[r];
    float* dst = (WHICH == 1) ? (float*)g_y1 : (float*)g_y2;
    atomicAdd(dst + 2 * c,     nrm * v.x);
    atomicAdd(dst + 2 * c + 1, nrm * v.y);
}

// out = log_softmax(y2 + b)  over C=2
__global__ void k_out(const float* __restrict__ b, float* __restrict__ out, int n) {
    int i = blockIdx.x * blockDim.x + threadIdx.x;
    if (i >= n) return;
    float2 y = g_y2[i];
    float l0 = y.x + b[0];
    float l1 = y.y + b[1];
    float m = fmaxf(l0, l1);
    float lse = m + logf(expf(l0 - m) + expf(l1 - m));
    out[2 * i]     = l0 - lse;
    out[2 * i + 1] = l1 - lse;
}

// ---------------- launch ----------------

extern "C" void kernel_launch(void* const* d_in, const int* in_sizes, int n_in,
                              void* d_out, int out_size) {
    const float* x    = (const float*)d_in[0];
    const void*  edge = d_in[1];
    const float* W    = (const float*)d_in[2];
    const float* b    = (const float*)d_in[3];
    float*       out  = (float*)d_out;

    int n = in_sizes[0] / DD;       // 100000
    int e = in_sizes[1] / 2;        // 1600000

    const int T = 256;
    int gn = (n + T - 1) / T;
    int ge = (e + T - 1) / T;
    int gw = (n * 32 + T - 1) / T;  // warp-per-node for projection

    k_detect<<<1, 1>>>(edge, n);
    k_init_deg<<<gn, T>>>(n);
    k_count<<<ge, T>>>(edge, e, n);
    k_dinv<<<gn, T>>>(n);
    k_proj<<<gw, T>>>(x, W, n);

    k_self<1><<<gn, T>>>(n);
    k_edge<1><<<ge, T>>>(e, n);

    k_self<2><<<gn, T>>>(n);
    k_edge<2><<<ge, T>>>(e, n);

    k_out<<<gn, T>>>(b, out, n);
}

// round 3
// speedup vs baseline: 1.2562x; 1.2562x over previous
#include <cuda_runtime.h>
#include <cuda_bf16.h>
#include <math.h>

#define NN 100000
#define EE 1600000
#define DD 64
#define CC 2

// Static device scratch (no allocation allowed)
__device__ int2   g_rc[EE];     // packed (row, col) per edge
__device__ float  g_nrm[EE];    // dinv[row]*dinv[col], written hop 1, reused hop 2
__device__ int    g_deg[NN];
__device__ float  g_dinv[NN];
__device__ float2 g_y0[NN];
__device__ float2 g_y1[NN];
__device__ float2 g_y2[NN];
__device__ int    g_is64;

// no-return vector float2 reduction (REDG, sm_90+)
__device__ __forceinline__ void red_add_f2(float2* p, float a, float b) {
    asm volatile("red.global.add.v2.f32 [%0], {%1, %2};"
                 :: "l"(p), "f"(a), "f"(b) : "memory");
}

// ---------------- kernels ----------------

// deg=1, y1=y2=0; thread (0,0) also detects edge dtype width.
__global__ void k_init(const void* __restrict__ edge, int n) {
    int i = blockIdx.x * blockDim.x + threadIdx.x;
    if (i == 0) {
        const long long* e64 = (const long long*)edge;
        int ok = 1;
        #pragma unroll 1
        for (int k = 0; k < 64; k++) {
            long long v = e64[k];
            if (v < 0 || v >= (long long)n) { ok = 0; break; }
        }
        g_is64 = ok;
    }
    if (i < n) {
        g_deg[i] = 1;
        g_y1[i] = make_float2(0.f, 0.f);
        g_y2[i] = make_float2(0.f, 0.f);
    }
}

// convert edge_index -> packed int2, count in-degree. 4 edges per thread.
__global__ void k_count(const void* __restrict__ edge, int e, int n) {
    int base = (blockIdx.x * blockDim.x + threadIdx.x) * 4;
    if (base >= e) return;
    int is64 = g_is64;
    int r[4], c[4];
    int m = min(4, e - base);
    if (is64) {
        const long long* e64 = (const long long*)edge;
        if (m == 4) {
            longlong2 r01 = *(const longlong2*)(e64 + base);
            longlong2 r23 = *(const longlong2*)(e64 + base + 2);
            longlong2 c01 = *(const longlong2*)(e64 + e + base);
            longlong2 c23 = *(const longlong2*)(e64 + e + base + 2);
            r[0] = (int)r01.x; r[1] = (int)r01.y; r[2] = (int)r23.x; r[3] = (int)r23.y;
            c[0] = (int)c01.x; c[1] = (int)c01.y; c[2] = (int)c23.x; c[3] = (int)c23.y;
        } else {
            for (int k = 0; k < m; k++) { r[k] = (int)e64[base + k]; c[k] = (int)e64[e + base + k]; }
        }
    } else {
        const int* e32 = (const int*)edge;
        if (m == 4) {
            int4 rr = *(const int4*)(e32 + base);
            int4 cc = *(const int4*)(e32 + e + base);
            r[0] = rr.x; r[1] = rr.y; r[2] = rr.z; r[3] = rr.w;
            c[0] = cc.x; c[1] = cc.y; c[2] = cc.z; c[3] = cc.w;
        } else {
            for (int k = 0; k < m; k++) { r[k] = e32[base + k]; c[k] = e32[e + base + k]; }
        }
    }
    #pragma unroll
    for (int k = 0; k < 4; k++) {
        if (k >= m) break;
        int rr = r[k], cc = c[k];
        if ((unsigned)rr >= (unsigned)n || (unsigned)cc >= (unsigned)n) { rr = 0; cc = 0; }
        g_rc[base + k] = make_int2(rr, cc);
        atomicAdd(&g_deg[cc], 1);
    }
}

// warp-per-node: dinv (lane 0) + projection y0 = x @ W.T
__global__ void k_proj(const float* __restrict__ x, const float* __restrict__ W, int n) {
    __shared__ float sW[2 * DD];
    int t = threadIdx.x;
    if (t < 2 * DD) sW[t] = W[t];
    __syncthreads();
    int gw = (blockIdx.x * blockDim.x + t) >> 5;
    int lane = t & 31;
    if (gw >= n) return;
    if (lane == 0) g_dinv[gw] = rsqrtf((float)g_deg[gw]);
    const float* xr = x + (size_t)gw * DD;
    float a  = xr[lane];
    float b2 = xr[lane + 32];
    float s0 = a * sW[lane]      + b2 * sW[lane + 32];
    float s1 = a * sW[DD + lane] + b2 * sW[DD + lane + 32];
    #pragma unroll
    for (int o = 16; o; o >>= 1) {
        s0 += __shfl_xor_sync(0xffffffffu, s0, o);
        s1 += __shfl_xor_sync(0xffffffffu, s1, o);
    }
    if (lane == 0) g_y0[gw] = make_float2(s0, s1);
}

// hop 1: y1[c] += dinv[r]*dinv[c]*y0[r]; edges [0,e) + self-loops [e,e+n).
// Also caches nrm for hop 2.
__global__ void k_edge1(int e, int n) {
    int i = blockIdx.x * blockDim.x + threadIdx.x;
    if (i < e) {
        int2 rc = g_rc[i];
        float nrm = g_dinv[rc.x] * g_dinv[rc.y];
        g_nrm[i] = nrm;
        float2 v = g_y0[rc.x];
        red_add_f2(&g_y1[rc.y], nrm * v.x, nrm * v.y);
    } else if (i < e + n) {
        int j = i - e;
        float d = g_dinv[j];
        float s = d * d;
        float2 v = g_y0[j];
        red_add_f2(&g_y1[j], s * v.x, s * v.y);
    }
}

// hop 2: y2[c] += nrm*y1[r] using cached nrm.
__global__ void k_edge2(int e, int n) {
    int i = blockIdx.x * blockDim.x + threadIdx.x;
    if (i < e) {
        int2 rc = g_rc[i];
        float nrm = g_nrm[i];
        float2 v = g_y1[rc.x];
        red_add_f2(&g_y2[rc.y], nrm * v.x, nrm * v.y);
    } else if (i < e + n) {
        int j = i - e;
        float d = g_dinv[j];
        float s = d * d;
        float2 v = g_y1[j];
        red_add_f2(&g_y2[j], s * v.x, s * v.y);
    }
}

// out = log_softmax(y2 + b) over C=2
__global__ void k_out(const float* __restrict__ b, float* __restrict__ out, int n) {
    int i = blockIdx.x * blockDim.x + threadIdx.x;
    if (i >= n) return;
    float2 y = g_y2[i];
    float l0 = y.x + b[0];
    float l1 = y.y + b[1];
    float m = fmaxf(l0, l1);
    float lse = m + logf(expf(l0 - m) + expf(l1 - m));
    float2 o = make_float2(l0 - lse, l1 - lse);
    *(float2*)(out + 2 * i) = o;
}

// ---------------- launch ----------------

extern "C" void kernel_launch(void* const* d_in, const int* in_sizes, int n_in,
                              void* d_out, int out_size) {
    const float* x    = (const float*)d_in[0];
    const void*  edge = d_in[1];
    const float* W    = (const float*)d_in[2];
    const float* b    = (const float*)d_in[3];
    float*       out  = (float*)d_out;

    int n = in_sizes[0] / DD;   // 100000
    int e = in_sizes[1] / 2;    // 1600000

    const int T = 256;
    int gn  = (n + T - 1) / T;
    int gc  = ((e + 3) / 4 + T - 1) / T;
    int gen = (e + n + T - 1) / T;
    int gw  = ((size_t)n * 32 + T - 1) / T;

    k_init<<<gn, T>>>(edge, n);
    k_count<<<gc, T>>>(edge, e, n);
    k_proj<<<gw, T>>>(x, W, n);
    k_edge1<<<gen, T>>>(e, n);
    k_edge2<<<gen, T>>>(e, n);
    k_out<<<gn, T>>>(b, out, n);
}

// round 4
// speedup vs baseline: 1.3737x; 1.0936x over previous
#include <cuda_runtime.h>
#include <cuda_bf16.h>
#include <math.h>

#define NN 100000
#define EE 1600000
#define DD 64
#define CC 2

// Static device scratch (no allocation allowed)
__device__ int2   g_rc[EE];     // packed (row, col) per edge
__device__ int    g_deg[NN];
__device__ float  g_dinv[NN];
__device__ float2 g_z0[NN];     // dinv[r] * (x[r] @ W.T)   (scaled source, hop 1)
__device__ float2 g_t1[NN];     // hop-1 accumulator; rescaled in place -> z1
__device__ float2 g_t2[NN];     // hop-2 accumulator
__device__ int    g_is64;

// no-return vector float2 reduction (REDG, sm_90+)
__device__ __forceinline__ void red_add_f2(float2* p, float a, float b) {
    asm volatile("red.global.add.v2.f32 [%0], {%1, %2};"
                 :: "l"(p), "f"(a), "f"(b) : "memory");
}

// ---------------- kernels ----------------

// deg=1, t1=t2=0; thread 0 detects edge dtype width.
__global__ void k_init(const void* __restrict__ edge, int n) {
    int i = blockIdx.x * blockDim.x + threadIdx.x;
    if (i == 0) {
        const long long* e64 = (const long long*)edge;
        int ok = 1;
        #pragma unroll 1
        for (int k = 0; k < 64; k++) {
            long long v = e64[k];
            if (v < 0 || v >= (long long)n) { ok = 0; break; }
        }
        g_is64 = ok;
    }
    if (i < n) {
        g_deg[i] = 1;
        g_t1[i] = make_float2(0.f, 0.f);
        g_t2[i] = make_float2(0.f, 0.f);
    }
}

// convert edge_index -> packed int2, count in-degree. 4 edges per thread.
__global__ void k_count(const void* __restrict__ edge, int e, int n) {
    int base = (blockIdx.x * blockDim.x + threadIdx.x) * 4;
    if (base >= e) return;
    int is64 = g_is64;
    int r[4], c[4];
    int m = min(4, e - base);
    if (is64) {
        const long long* e64 = (const long long*)edge;
        if (m == 4) {
            longlong2 r01 = *(const longlong2*)(e64 + base);
            longlong2 r23 = *(const longlong2*)(e64 + base + 2);
            longlong2 c01 = *(const longlong2*)(e64 + e + base);
            longlong2 c23 = *(const longlong2*)(e64 + e + base + 2);
            r[0] = (int)r01.x; r[1] = (int)r01.y; r[2] = (int)r23.x; r[3] = (int)r23.y;
            c[0] = (int)c01.x; c[1] = (int)c01.y; c[2] = (int)c23.x; c[3] = (int)c23.y;
        } else {
            for (int k = 0; k < m; k++) { r[k] = (int)e64[base + k]; c[k] = (int)e64[e + base + k]; }
        }
    } else {
        const int* e32 = (const int*)edge;
        if (m == 4) {
            int4 rr = *(const int4*)(e32 + base);
            int4 cc = *(const int4*)(e32 + e + base);
            r[0] = rr.x; r[1] = rr.y; r[2] = rr.z; r[3] = rr.w;
            c[0] = cc.x; c[1] = cc.y; c[2] = cc.z; c[3] = cc.w;
        } else {
            for (int k = 0; k < m; k++) { r[k] = e32[base + k]; c[k] = e32[e + base + k]; }
        }
    }
    #pragma unroll
    for (int k = 0; k < 4; k++) {
        if (k >= m) break;
        int rr = r[k], cc = c[k];
        if ((unsigned)rr >= (unsigned)n || (unsigned)cc >= (unsigned)n) { rr = 0; cc = 0; }
        g_rc[base + k] = make_int2(rr, cc);
        atomicAdd(&g_deg[cc], 1);
    }
}

// warp-per-node: dinv + scaled projection z0 = dinv * (x @ W.T)
__global__ void k_proj(const float* __restrict__ x, const float* __restrict__ W, int n) {
    __shared__ float sW[2 * DD];
    int t = threadIdx.x;
    if (t < 2 * DD) sW[t] = W[t];
    __syncthreads();
    int gw = (blockIdx.x * blockDim.x + t) >> 5;
    int lane = t & 31;
    if (gw >= n) return;
    const float* xr = x + (size_t)gw * DD;
    float a  = xr[lane];
    float b2 = xr[lane + 32];
    float s0 = a * sW[lane]      + b2 * sW[lane + 32];
    float s1 = a * sW[DD + lane] + b2 * sW[DD + lane + 32];
    #pragma unroll
    for (int o = 16; o; o >>= 1) {
        s0 += __shfl_xor_sync(0xffffffffu, s0, o);
        s1 += __shfl_xor_sync(0xffffffffu, s1, o);
    }
    if (lane == 0) {
        float d = rsqrtf((float)g_deg[gw]);
        g_dinv[gw] = d;
        g_z0[gw] = make_float2(d * s0, d * s1);
    }
}

// edge scatter: t[c] += z[r] over edges [0,e), self-loops as tail [e, e+n)
template <int HOP>  // 1: z0 -> t1, 2: t1(=z1) -> t2
__global__ void k_edge(int e, int n) {
    int i = blockIdx.x * blockDim.x + threadIdx.x;
    const float2* z = (HOP == 1) ? g_z0 : g_t1;
    float2*       t = (HOP == 1) ? g_t1 : g_t2;
    if (i < e) {
        int2 rc = g_rc[i];
        float2 v = __ldg(&z[rc.x]);
        red_add_f2(&t[rc.y], v.x, v.y);
    } else if (i < e + n) {
        int j = i - e;
        float2 v = __ldg(&z[j]);
        red_add_f2(&t[j], v.x, v.y);
    }
}

// rescale between hops: t1 <- dinv^2 * t1  (= z1)
__global__ void k_mid(int n) {
    int i = blockIdx.x * blockDim.x + threadIdx.x;
    if (i >= n) return;
    float d = g_dinv[i];
    float s = d * d;
    float2 v = g_t1[i];
    g_t1[i] = make_float2(s * v.x, s * v.y);
}

// out = log_softmax(dinv * t2 + b) over C=2
__global__ void k_out(const float* __restrict__ b, float* __restrict__ out, int n) {
    int i = blockIdx.x * blockDim.x + threadIdx.x;
    if (i >= n) return;
    float d = g_dinv[i];
    float2 y = g_t2[i];
    float l0 = d * y.x + b[0];
    float l1 = d * y.y + b[1];
    float m = fmaxf(l0, l1);
    float lse = m + logf(expf(l0 - m) + expf(l1 - m));
    *(float2*)(out + 2 * i) = make_float2(l0 - lse, l1 - lse);
}

// ---------------- launch ----------------

extern "C" void kernel_launch(void* const* d_in, const int* in_sizes, int n_in,
                              void* d_out, int out_size) {
    const float* x    = (const float*)d_in[0];
    const void*  edge = d_in[1];
    const float* W    = (const float*)d_in[2];
    const float* b    = (const float*)d_in[3];
    float*       out  = (float*)d_out;

    int n = in_sizes[0] / DD;   // 100000
    int e = in_sizes[1] / 2;    // 1600000

    const int T = 256;
    int gn  = (n + T - 1) / T;
    int gc  = ((e + 3) / 4 + T - 1) / T;
    int gen = (e + n + T - 1) / T;
    int gw  = ((size_t)n * 32 + T - 1) / T;

    k_init<<<gn, T>>>(edge, n);
    k_count<<<gc, T>>>(edge, e, n);
    k_proj<<<gw, T>>>(x, W, n);
    k_edge<1><<<gen, T>>>(e, n);
    k_mid<<<gn, T>>>(n);
    k_edge<2><<<gen, T>>>(e, n);
    k_out<<<gn, T>>>(b, out, n);
}